// round 2
// baseline (speedup 1.0000x reference)
#include <cuda_runtime.h>

// Problem constants
constexpr int NROWS = 16384;
constexpr int DIM   = 128;
constexpr int TOPK  = 32;
constexpr int SLAB  = 1024;            // rows per slab
constexpr int NSLABS = NROWS / SLAB;   // 16
constexpr long long NKTOT = (long long)NROWS * TOPK;  // 524288

// 64 MB scratch for one slab of the adjacency matrix (sanctioned: __device__ global)
__device__ float g_scratch[(size_t)SLAB * NROWS];

// ---------------- packed f32x2 helpers (Blackwell FFMA2) ----------------
__device__ __forceinline__ unsigned long long pack_dup(float x) {
    unsigned long long r;
    asm("mov.b64 %0, {%1, %1};" : "=l"(r) : "r"(__float_as_uint(x)));
    return r;
}
__device__ __forceinline__ void ffma2(unsigned long long& d,
                                      unsigned long long a,
                                      unsigned long long b) {
    asm("fma.rn.f32x2 %0, %1, %2, %0;" : "+l"(d) : "l"(a), "l"(b));
}
__device__ __forceinline__ float2 unpack2(unsigned long long x) {
    float2 r;
    asm("mov.b64 {%0, %1}, %2;" : "=f"(r.x), "=f"(r.y) : "l"(x));
    return r;
}

// ---------------- GEMM: one 128x128 tile per CTA, full K=128 in smem ----------------
// As/Bs stored transposed: [k][row] so compute-phase LDS are broadcast/conflict-free.
__global__ __launch_bounds__(256) void gemm_slab_kernel(const float* __restrict__ W,
                                                        int rowBase) {
    extern __shared__ float sm[];
    float* As = sm;            // [128][128]  As[k][r] = W[rowA0+r][k]
    float* Bs = sm + 128 * 128;

    const int tid   = threadIdx.x;
    const int rowA0 = rowBase + blockIdx.y * 128;
    const int rowB0 = blockIdx.x * 128;

#pragma unroll
    for (int it = 0; it < 16; ++it) {
        int linear = tid + it * 256;   // 0..4095
        int r  = linear & 127;
        int k4 = linear >> 7;          // 0..31
        float4 a = *(const float4*)(W + ((size_t)(rowA0 + r) << 7) + (k4 << 2));
        float4 b = *(const float4*)(W + ((size_t)(rowB0 + r) << 7) + (k4 << 2));
        As[(k4 * 4 + 0) * 128 + r] = a.x;
        As[(k4 * 4 + 1) * 128 + r] = a.y;
        As[(k4 * 4 + 2) * 128 + r] = a.z;
        As[(k4 * 4 + 3) * 128 + r] = a.w;
        Bs[(k4 * 4 + 0) * 128 + r] = b.x;
        Bs[(k4 * 4 + 1) * 128 + r] = b.y;
        Bs[(k4 * 4 + 2) * 128 + r] = b.z;
        Bs[(k4 * 4 + 3) * 128 + r] = b.w;
    }
    __syncthreads();

    const int tx = tid & 15, ty = tid >> 4;   // 16x16 threads, 8x8 microtile
    unsigned long long acc[8][4];
#pragma unroll
    for (int i = 0; i < 8; ++i)
#pragma unroll
        for (int j = 0; j < 4; ++j) acc[i][j] = 0ULL;

    const float* aBase = As + ty * 8;
    const float* bBase = Bs + tx * 8;

#pragma unroll 4
    for (int k = 0; k < 128; ++k) {
        float4 a0 = *(const float4*)(aBase + k * 128);
        float4 a1 = *(const float4*)(aBase + k * 128 + 4);
        ulonglong2 bb0 = *(const ulonglong2*)(bBase + k * 128);
        ulonglong2 bb1 = *(const ulonglong2*)(bBase + k * 128 + 4);
        unsigned long long bv[4] = {bb0.x, bb0.y, bb1.x, bb1.y};
        float av[8] = {a0.x, a0.y, a0.z, a0.w, a1.x, a1.y, a1.z, a1.w};
#pragma unroll
        for (int i = 0; i < 8; ++i) {
            unsigned long long ad = pack_dup(av[i]);
#pragma unroll
            for (int j = 0; j < 4; ++j) ffma2(acc[i][j], ad, bv[j]);
        }
    }

    const int slabRow0 = blockIdx.y * 128 + ty * 8;   // slab-local row
    const int col0 = rowB0 + tx * 8;
#pragma unroll
    for (int i = 0; i < 8; ++i) {
        float2 c0 = unpack2(acc[i][0]);
        float2 c1 = unpack2(acc[i][1]);
        float2 c2 = unpack2(acc[i][2]);
        float2 c3 = unpack2(acc[i][3]);
        float* p = g_scratch + (size_t)(slabRow0 + i) * NROWS + col0;
        *(float4*)p       = make_float4(c0.x, c0.y, c1.x, c1.y);
        *(float4*)(p + 4) = make_float4(c2.x, c2.y, c3.x, c3.y);
    }
}

// ---------------- exact per-row top-32 via 3-level radix select ----------------
__device__ __forceinline__ void find_bin(unsigned* hist, unsigned* ssum,
                                         unsigned* sBin, unsigned* sAbove,
                                         int nbins, int target) {
    const int tid = threadIdx.x;
    const int bpt = nbins >> 9;   // bins per thread (512 threads)
    unsigned s = 0;
    const int b0 = tid * bpt;
    for (int i = 0; i < bpt; ++i) s += hist[b0 + i];
    ssum[tid] = s;
    __syncthreads();
    // Hillis-Steele inclusive suffix sum
    for (int off = 1; off < 512; off <<= 1) {
        unsigned v = (tid + off < 512) ? ssum[tid + off] : 0u;
        __syncthreads();
        ssum[tid] += v;
        __syncthreads();
    }
    unsigned cumAbove = ssum[tid] - s;   // strictly above this thread's bin range
    if (cumAbove < (unsigned)target && cumAbove + s >= (unsigned)target) {
        unsigned c = cumAbove;
        for (int b = b0 + bpt - 1;; --b) {
            unsigned h = hist[b];
            if (c + h >= (unsigned)target) { *sBin = (unsigned)b; *sAbove = c; break; }
            c += h;
        }
    }
    __syncthreads();
}

__global__ __launch_bounds__(512) void select_kernel(float* __restrict__ out,
                                                     int rowBase) {
    __shared__ unsigned hist[2048];
    __shared__ unsigned ssum[512];
    __shared__ unsigned sBin, sAbove, sOutBase, sEqSeen;

    const int tid = threadIdx.x;
    const int row_local = blockIdx.x;
    const int row = rowBase + row_local;
    const float* rp = g_scratch + (size_t)row_local * NROWS;

    // load + build monotonic keys (index j = c*512 + tid -> tid-order == index order)
    unsigned keys[32];
#pragma unroll
    for (int c = 0; c < 32; ++c) {
        unsigned u = __float_as_uint(rp[c * 512 + tid]);
        keys[c] = u ^ (unsigned)((((int)u) >> 31) | 0x80000000);
    }

    // Level 1: bits [31:21]
    for (int b = tid; b < 2048; b += 512) hist[b] = 0;
    __syncthreads();
#pragma unroll
    for (int c = 0; c < 32; ++c) atomicAdd(&hist[keys[c] >> 21], 1u);
    __syncthreads();
    find_bin(hist, ssum, &sBin, &sAbove, 2048, TOPK);
    const unsigned B1 = sBin;
    const int target2 = TOPK - (int)sAbove;

    // Level 2: bits [20:10] within B1
    for (int b = tid; b < 2048; b += 512) hist[b] = 0;
    __syncthreads();
#pragma unroll
    for (int c = 0; c < 32; ++c)
        if ((keys[c] >> 21) == B1) atomicAdd(&hist[(keys[c] >> 10) & 2047], 1u);
    __syncthreads();
    find_bin(hist, ssum, &sBin, &sAbove, 2048, target2);
    const unsigned B2 = sBin;
    const int target3 = target2 - (int)sAbove;
    const unsigned pref = (B1 << 11) | B2;

    // Level 3: bits [9:0] within (B1,B2)
    for (int b = tid; b < 1024; b += 512) hist[b] = 0;
    __syncthreads();
#pragma unroll
    for (int c = 0; c < 32; ++c)
        if ((keys[c] >> 10) == pref) atomicAdd(&hist[keys[c] & 1023], 1u);
    __syncthreads();
    find_bin(hist, ssum, &sBin, &sAbove, 1024, target3);
    const unsigned Kkey = (pref << 10) | sBin;   // exact 32nd-largest key
    const int needEq = target3 - (int)sAbove;    // ties to take (lowest index first)

    // Emit in index order with block-wide compaction (output is naturally col-sorted)
    if (tid == 0) { sOutBase = 0; sEqSeen = 0; }
    const int lane = tid & 31, warp = tid >> 5;
    const unsigned ltmask = (1u << lane) - 1u;
    __syncthreads();

#pragma unroll
    for (int c = 0; c < 32; ++c) {
        const unsigned k = keys[c];
        const bool gt = k > Kkey;
        const bool eq = (k == Kkey);
        unsigned meq = __ballot_sync(0xffffffffu, eq);
        if (lane == 0) ssum[warp] = __popc(meq);
        __syncthreads();
        unsigned eqPref = 0, eqTot = 0;
        for (int w = 0; w < 16; ++w) {
            unsigned x = ssum[w];
            eqTot += x;
            if (w < warp) eqPref += x;
        }
        const unsigned eqRank = sEqSeen + eqPref + __popc(meq & ltmask);
        const bool inc = gt || (eq && eqRank < (unsigned)needEq);
        unsigned minc = __ballot_sync(0xffffffffu, inc);
        if (lane == 0) ssum[16 + warp] = __popc(minc);
        __syncthreads();
        unsigned incPref = 0, incTot = 0;
        for (int w = 0; w < 16; ++w) {
            unsigned x = ssum[16 + w];
            incTot += x;
            if (w < warp) incPref += x;
        }
        if (inc) {
            const unsigned pos = sOutBase + incPref + __popc(minc & ltmask);
            const int j = c * 512 + tid;
            unsigned u = (k & 0x80000000u) ? (k ^ 0x80000000u) : ~k;
            const long long o = (long long)row * TOPK + pos;
            out[o]             = (float)row;          // edge_index[0]
            out[NKTOT + o]     = (float)j;            // edge_index[1] (sorted cols)
            out[2 * NKTOT + o] = __uint_as_float(u);  // edge_values
        }
        __syncthreads();
        if (tid == 0) { sOutBase += incTot; sEqSeen += eqTot; }
        __syncthreads();
    }
}

// ---------------- launch ----------------
extern "C" void kernel_launch(void* const* d_in, const int* in_sizes, int n_in,
                              void* d_out, int out_size) {
    // inputs: x [16384] (unused), W [16384*128]; pick W by size to be safe
    const float* W = (const float*)d_in[n_in > 1 ? 1 : 0];
    if (in_sizes[0] == NROWS * DIM) W = (const float*)d_in[0];
    float* out = (float*)d_out;

    cudaFuncSetAttribute(gemm_slab_kernel,
                         cudaFuncAttributeMaxDynamicSharedMemorySize, 131072);

    for (int s = 0; s < NSLABS; ++s) {
        gemm_slab_kernel<<<dim3(NROWS / 128, SLAB / 128), 256, 131072>>>(W, s * SLAB);
        select_kernel<<<SLAB, 512>>>(out, s * SLAB);
    }
}

// round 4
// speedup vs baseline: 1.5912x; 1.5912x over previous
#include <cuda_runtime.h>

// Problem constants
constexpr int NROWS = 16384;
constexpr int DIM   = 128;
constexpr int TOPK  = 32;
constexpr int SLAB  = 1024;            // rows per slab
constexpr int NSLABS = NROWS / SLAB;   // 16
constexpr long long NKTOT = (long long)NROWS * TOPK;  // 524288

// 64 MB scratch for one slab of the adjacency matrix (sanctioned: __device__ global)
__device__ float g_scratch[(size_t)SLAB * NROWS];

// ---------------- packed f32x2 helpers (Blackwell FFMA2) ----------------
__device__ __forceinline__ unsigned long long pack_dup(float x) {
    unsigned long long r;
    asm("mov.b64 %0, {%1, %1};" : "=l"(r) : "r"(__float_as_uint(x)));
    return r;
}
__device__ __forceinline__ void ffma2(unsigned long long& d,
                                      unsigned long long a,
                                      unsigned long long b) {
    asm("fma.rn.f32x2 %0, %1, %2, %0;" : "+l"(d) : "l"(a), "l"(b));
}
__device__ __forceinline__ float2 unpack2(unsigned long long x) {
    float2 r;
    asm("mov.b64 {%0, %1}, %2;" : "=f"(r.x), "=f"(r.y) : "l"(x));
    return r;
}

// ---------------- GEMM: one 128x128 tile per CTA, full K=128 in smem ----------------
__global__ __launch_bounds__(256) void gemm_slab_kernel(const float* __restrict__ W,
                                                        int rowBase) {
    extern __shared__ float sm[];
    float* As = sm;            // [128][128]  As[k][r] = W[rowA0+r][k]
    float* Bs = sm + 128 * 128;

    const int tid   = threadIdx.x;
    const int rowA0 = rowBase + blockIdx.y * 128;
    const int rowB0 = blockIdx.x * 128;

#pragma unroll
    for (int it = 0; it < 16; ++it) {
        int linear = tid + it * 256;   // 0..4095
        int r  = linear & 127;
        int k4 = linear >> 7;          // 0..31
        float4 a = *(const float4*)(W + ((size_t)(rowA0 + r) << 7) + (k4 << 2));
        float4 b = *(const float4*)(W + ((size_t)(rowB0 + r) << 7) + (k4 << 2));
        As[(k4 * 4 + 0) * 128 + r] = a.x;
        As[(k4 * 4 + 1) * 128 + r] = a.y;
        As[(k4 * 4 + 2) * 128 + r] = a.z;
        As[(k4 * 4 + 3) * 128 + r] = a.w;
        Bs[(k4 * 4 + 0) * 128 + r] = b.x;
        Bs[(k4 * 4 + 1) * 128 + r] = b.y;
        Bs[(k4 * 4 + 2) * 128 + r] = b.z;
        Bs[(k4 * 4 + 3) * 128 + r] = b.w;
    }
    __syncthreads();

    const int tx = tid & 15, ty = tid >> 4;   // 16x16 threads, 8x8 microtile
    unsigned long long acc[8][4];
#pragma unroll
    for (int i = 0; i < 8; ++i)
#pragma unroll
        for (int j = 0; j < 4; ++j) acc[i][j] = 0ULL;

    const float* aBase = As + ty * 8;
    const float* bBase = Bs + tx * 8;

#pragma unroll 4
    for (int k = 0; k < 128; ++k) {
        float4 a0 = *(const float4*)(aBase + k * 128);
        float4 a1 = *(const float4*)(aBase + k * 128 + 4);
        ulonglong2 bb0 = *(const ulonglong2*)(bBase + k * 128);
        ulonglong2 bb1 = *(const ulonglong2*)(bBase + k * 128 + 4);
        unsigned long long bv[4] = {bb0.x, bb0.y, bb1.x, bb1.y};
        float av[8] = {a0.x, a0.y, a0.z, a0.w, a1.x, a1.y, a1.z, a1.w};
#pragma unroll
        for (int i = 0; i < 8; ++i) {
            unsigned long long ad = pack_dup(av[i]);
#pragma unroll
            for (int j = 0; j < 4; ++j) ffma2(acc[i][j], ad, bv[j]);
        }
    }

    const int slabRow0 = blockIdx.y * 128 + ty * 8;   // slab-local row
    const int col0 = rowB0 + tx * 8;
#pragma unroll
    for (int i = 0; i < 8; ++i) {
        float2 c0 = unpack2(acc[i][0]);
        float2 c1 = unpack2(acc[i][1]);
        float2 c2 = unpack2(acc[i][2]);
        float2 c3 = unpack2(acc[i][3]);
        float* p = g_scratch + (size_t)(slabRow0 + i) * NROWS + col0;
        *(float4*)p       = make_float4(c0.x, c0.y, c1.x, c1.y);
        *(float4*)(p + 4) = make_float4(c2.x, c2.y, c3.x, c3.y);
    }
}

// ---------------- exact per-row top-32 via pivot prefilter + small exact rank ----------------
// monotonic key: order-preserving uint mapping of float
__device__ __forceinline__ unsigned f2key(float f) {
    unsigned u = __float_as_uint(f);
    return u ^ (unsigned)((((int)u) >> 31) | 0x80000000);
}
__device__ __forceinline__ float key2f(unsigned k) {
    unsigned u = (k & 0x80000000u) ? (k ^ 0x80000000u) : ~k;
    return __uint_as_float(u);
}

constexpr int CAND_CAP = 1024;

__global__ __launch_bounds__(512) void select_kernel(float* __restrict__ out,
                                                     int rowBase) {
    __shared__ unsigned candK[CAND_CAP];
    __shared__ unsigned candI[CAND_CAP];
    __shared__ unsigned flags[CAND_CAP];
    __shared__ unsigned sWarp2[16];
    __shared__ unsigned sKeyT;
    __shared__ unsigned sCnt;

    const int tid  = threadIdx.x;
    const int lane = tid & 31, warp = tid >> 5;
    const int row_local = blockIdx.x;
    const int row = rowBase + row_local;
    // each thread owns 32 CONTIGUOUS columns [tid*32, tid*32+32)
    const float4* rp = (const float4*)(g_scratch + (size_t)row_local * NROWS) + tid * 8;

    if (tid == 0) sCnt = 0;

    // ---- phase 1: per-thread top-2 (monotonic keys), warp merge, block min of warp-2nd-max
    unsigned m1 = 0, m2 = 0;
#pragma unroll
    for (int q = 0; q < 8; ++q) {
        float4 v = rp[q];
        float vv[4] = {v.x, v.y, v.z, v.w};
#pragma unroll
        for (int e = 0; e < 4; ++e) {
            unsigned k = f2key(vv[e]);
            if (k > m1) { m2 = m1; m1 = k; }
            else if (k > m2) m2 = k;
        }
    }
#pragma unroll
    for (int off = 16; off > 0; off >>= 1) {
        unsigned o1 = __shfl_down_sync(0xffffffffu, m1, off);
        unsigned o2 = __shfl_down_sync(0xffffffffu, m2, off);
        unsigned n1 = m1 > o1 ? m1 : o1;
        unsigned n2;
        if (m1 > o1) { n2 = (m2 > o1) ? m2 : o1; }
        else         { n2 = (o2 > m1) ? o2 : m1; }
        m1 = n1; m2 = n2;
    }
    if (lane == 0) sWarp2[warp] = m2;
    __syncthreads();
    if (warp == 0) {
        unsigned v = (lane < 16) ? sWarp2[lane] : 0xffffffffu;
#pragma unroll
        for (int off = 8; off > 0; off >>= 1) {
            unsigned o = __shfl_down_sync(0xffffffffu, v, off);
            v = o < v ? o : v;
        }
        if (lane == 0) sKeyT = v;
    }
    __syncthreads();
    const unsigned keyT = sKeyT;   // every warp's top-2 >= keyT  =>  >=32 candidates,
                                   // and the true 32nd-largest >= keyT (exactness)

    // ---- phase 2: compact candidates (expected ~80 per row)
#pragma unroll
    for (int q = 0; q < 8; ++q) {
        float4 v = rp[q];
        float vv[4] = {v.x, v.y, v.z, v.w};
#pragma unroll
        for (int e = 0; e < 4; ++e) {
            unsigned k = f2key(vv[e]);
            if (k >= keyT) {
                unsigned p = atomicAdd(&sCnt, 1u);
                if (p < CAND_CAP) {
                    candK[p] = k;
                    candI[p] = (unsigned)(tid * 32 + q * 4 + e);
                }
            }
        }
    }
    __syncthreads();
    const int C = (int)(sCnt < CAND_CAP ? sCnt : CAND_CAP);

    // ---- phase 3: exact rank among C candidates, tie-break lowest index (stable top_k)
    unsigned myk = 0, myi = 0;
    int rank = 0;
    if (tid < C) { myk = candK[tid]; myi = candI[tid]; }
    for (int j = 0; j < C; ++j) {                 // broadcast LDS reads
        unsigned ck = candK[j], ci = candI[j];
        if (tid < C)
            rank += (ck > myk) || (ck == myk && ci < myi);
    }
    if (tid < C) flags[tid] = (rank < TOPK) ? 1u : 0u;
    __syncthreads();

    // position among winners = #winners with smaller column index -> column-sorted output
    if (tid < C && rank < TOPK) {
        int pos = 0;
        for (int j = 0; j < C; ++j)
            pos += (flags[j] && candI[j] < myi);
        const long long o = (long long)row * TOPK + pos;
        out[o]             = (float)row;        // edge_index[0]
        out[NKTOT + o]     = (float)myi;        // edge_index[1]
        out[2 * NKTOT + o] = key2f(myk);        // edge_values
    }
}

// ---------------- launch ----------------
extern "C" void kernel_launch(void* const* d_in, const int* in_sizes, int n_in,
                              void* d_out, int out_size) {
    const float* W = (const float*)d_in[n_in > 1 ? 1 : 0];
    if (in_sizes[0] == NROWS * DIM) W = (const float*)d_in[0];
    float* out = (float*)d_out;

    cudaFuncSetAttribute(gemm_slab_kernel,
                         cudaFuncAttributeMaxDynamicSharedMemorySize, 131072);

    for (int s = 0; s < NSLABS; ++s) {
        gemm_slab_kernel<<<dim3(NROWS / 128, SLAB / 128), 256, 131072>>>(W, s * SLAB);
        select_kernel<<<SLAB, 512>>>(out, s * SLAB);
    }
}

// round 6
// speedup vs baseline: 2.5800x; 1.6214x over previous
#include <cuda_runtime.h>
#include <cuda_bf16.h>
#include <cstdint>

// Problem constants
constexpr int NROWS = 16384;
constexpr int DIM   = 128;
constexpr int TOPK  = 32;
constexpr int SLAB  = 1024;
constexpr int NSLABS = NROWS / SLAB;
constexpr long long NKTOT = (long long)NROWS * TOPK;

constexpr int KCAT = 384;           // 3 x 128 (hi|lo|hi vs hi|hi|lo)
constexpr int NKSTEP = KCAT / 16;   // 24 mma k-steps of K=16

// scratch (sanctioned __device__ globals)
__device__ __align__(128) float g_scratch[(size_t)SLAB * NROWS];              // 64 MB
__device__ __align__(128) __nv_bfloat16 g_Acat[(size_t)NROWS * KCAT];         // 12 MB
__device__ __align__(128) __nv_bfloat16 g_Bcat[(size_t)NROWS * KCAT];         // 12 MB

// ---------------- prep: build split operand tables ----------------
__global__ __launch_bounds__(256) void prep_kernel(const float* __restrict__ W) {
    int t = blockIdx.x * 256 + threadIdx.x;
    if (t >= NROWS * DIM) return;
    int row = t >> 7, j = t & 127;
    float w = W[t];
    __nv_bfloat16 hi = __float2bfloat16(w);
    float r = w - __bfloat162float(hi);
    __nv_bfloat16 lo = __float2bfloat16(r);
    size_t base = (size_t)row * KCAT;
    g_Acat[base + j]       = hi;
    g_Acat[base + 128 + j] = lo;
    g_Acat[base + 256 + j] = hi;
    g_Bcat[base + j]       = hi;
    g_Bcat[base + 128 + j] = hi;
    g_Bcat[base + 256 + j] = lo;
}

// ---------------- HMMA GEMM: 128x128 tile/CTA, K=384, mma.sync bf16 ----------------
// smem: A tile [128][392] bf16 (row pad +8 -> 784B stride), B tile same.
constexpr int SA = 392;                       // bf16 units per smem row (784 B)
constexpr int A_BYTES = 128 * SA * 2;         // 100352
constexpr int GEMM_SMEM = 2 * A_BYTES;        // 200704

__device__ __forceinline__ void mma16816(float* c, const uint32_t* a, const uint32_t* b) {
    asm volatile(
        "mma.sync.aligned.m16n8k16.row.col.f32.bf16.bf16.f32 "
        "{%0,%1,%2,%3}, {%4,%5,%6,%7}, {%8,%9}, {%0,%1,%2,%3};"
        : "+f"(c[0]), "+f"(c[1]), "+f"(c[2]), "+f"(c[3])
        : "r"(a[0]), "r"(a[1]), "r"(a[2]), "r"(a[3]), "r"(b[0]), "r"(b[1]));
}

__global__ __launch_bounds__(256) void gemm_kernel(int rowBase) {
    extern __shared__ __nv_bfloat16 sm[];
    __nv_bfloat16* As = sm;
    __nv_bfloat16* Bs = sm + 128 * SA;

    const int tid  = threadIdx.x;
    const int lane = tid & 31, w = tid >> 5;
    const int wm = w >> 2, wn = w & 3;        // warp grid 2x4, warp tile 64x32
    const int g = lane >> 2, tig = lane & 3;
    const int rowA0 = rowBase + blockIdx.y * 128;
    const int rowB0 = blockIdx.x * 128;

    // ---- load tiles (16B chunks, coalesced gmem, sequential smem)
    const char* Ag = (const char*)g_Acat + (size_t)rowA0 * 768;
    const char* Bg = (const char*)g_Bcat + (size_t)rowB0 * 768;
#pragma unroll
    for (int it = 0; it < 24; ++it) {
        int i = tid + it * 256;               // 0..6143
        int r = i / 48, c = i % 48;           // row, 16B chunk
        uint4 va = *(const uint4*)(Ag + (size_t)r * 768 + c * 16);
        uint4 vb = *(const uint4*)(Bg + (size_t)r * 768 + c * 16);
        *(uint4*)((char*)As + r * 784 + c * 16) = va;
        *(uint4*)((char*)Bs + r * 784 + c * 16) = vb;
    }
    __syncthreads();

    // ---- mainloop: 24 k-steps, per warp 4x4 mma frags (64x32)
    float acc[4][4][4];
#pragma unroll
    for (int mi = 0; mi < 4; ++mi)
#pragma unroll
        for (int ni = 0; ni < 4; ++ni)
#pragma unroll
            for (int e = 0; e < 4; ++e) acc[mi][ni][e] = 0.f;

    const __nv_bfloat16* aB = As + (wm * 64 + g) * SA + tig * 2;
    const __nv_bfloat16* bB = Bs + (wn * 32 + g) * SA + tig * 2;

#pragma unroll 4
    for (int s = 0; s < NKSTEP; ++s) {
        const int kb = s * 16;
        uint32_t af[4][4], bf[4][2];
#pragma unroll
        for (int mi = 0; mi < 4; ++mi) {
            const __nv_bfloat16* p = aB + mi * 16 * SA + kb;
            af[mi][0] = *(const uint32_t*)(p);
            af[mi][1] = *(const uint32_t*)(p + 8 * SA);
            af[mi][2] = *(const uint32_t*)(p + 8);
            af[mi][3] = *(const uint32_t*)(p + 8 * SA + 8);
        }
#pragma unroll
        for (int ni = 0; ni < 4; ++ni) {
            const __nv_bfloat16* p = bB + ni * 8 * SA + kb;
            bf[ni][0] = *(const uint32_t*)(p);
            bf[ni][1] = *(const uint32_t*)(p + 8);
        }
#pragma unroll
        for (int mi = 0; mi < 4; ++mi)
#pragma unroll
            for (int ni = 0; ni < 4; ++ni)
                mma16816(acc[mi][ni], af[mi], bf[ni]);
    }
    __syncthreads();

    // ---- stage accumulators to smem (reuse As region), stride 132 floats
    float* st = (float*)sm;
#pragma unroll
    for (int mi = 0; mi < 4; ++mi)
#pragma unroll
        for (int ni = 0; ni < 4; ++ni) {
            int r0 = wm * 64 + mi * 16 + g;
            int c0 = wn * 32 + ni * 8 + tig * 2;
            *(float2*)(st + r0 * 132 + c0)       = make_float2(acc[mi][ni][0], acc[mi][ni][1]);
            *(float2*)(st + (r0 + 8) * 132 + c0) = make_float2(acc[mi][ni][2], acc[mi][ni][3]);
        }
    __syncthreads();

    // ---- coalesced copy staging -> scratch
    float* outp = g_scratch + (size_t)(blockIdx.y * 128) * NROWS + rowB0;
#pragma unroll
    for (int it = 0; it < 16; ++it) {
        int i = tid + it * 256;               // 0..4095 float4 slots
        int r = i >> 5, c4 = i & 31;
        float4 v = *(const float4*)(st + r * 132 + c4 * 4);
        *(float4*)(outp + (size_t)r * NROWS + c4 * 4) = v;
    }
}

// ---------------- select: pivot prefilter (approx) + exact fp32 re-rank ----------------
__device__ __forceinline__ unsigned f2key(float f) {
    unsigned u = __float_as_uint(f);
    return u ^ (unsigned)((((int)u) >> 31) | 0x80000000);
}

constexpr int CAND_CAP = 1024;
constexpr float DELTA = 0.05f;   // guard band >> worst-case split-GEMM error (~0.012)

__global__ __launch_bounds__(512) void select_kernel(const float* __restrict__ W,
                                                     float* __restrict__ out,
                                                     int rowBase) {
    __shared__ unsigned candI[CAND_CAP];
    __shared__ unsigned candK[CAND_CAP];
    __shared__ float    candV[CAND_CAP];
    __shared__ unsigned flags[CAND_CAP];
    __shared__ float sWrow[128];
    __shared__ float sWarp2[16];
    __shared__ float sThr;
    __shared__ unsigned sCnt;

    const int tid = threadIdx.x;
    const int lane = tid & 31, warp = tid >> 5;
    const int row_local = blockIdx.x;
    const int row = rowBase + row_local;

    if (tid == 0) sCnt = 0;
    if (tid < 32) {
        float4 wv = *((const float4*)(W + (size_t)row * DIM) + tid);
        *((float4*)sWrow + tid) = wv;
    }

    const float4* rp = (const float4*)(g_scratch + (size_t)row_local * NROWS) + tid * 8;
    float4 q[8];
#pragma unroll
    for (int i = 0; i < 8; ++i) q[i] = rp[i];

    // phase 1: per-thread top-2, warp merge, block-min of warp 2nd-max
    float m1 = -3.4e38f, m2 = -3.4e38f;
#pragma unroll
    for (int i = 0; i < 8; ++i) {
        float vv[4] = {q[i].x, q[i].y, q[i].z, q[i].w};
#pragma unroll
        for (int e = 0; e < 4; ++e) {
            float v = vv[e];
            if (v > m1) { m2 = m1; m1 = v; }
            else if (v > m2) m2 = v;
        }
    }
#pragma unroll
    for (int off = 16; off > 0; off >>= 1) {
        float o1 = __shfl_down_sync(0xffffffffu, m1, off);
        float o2 = __shfl_down_sync(0xffffffffu, m2, off);
        float n1 = m1 > o1 ? m1 : o1;
        float n2 = (m1 > o1) ? (m2 > o1 ? m2 : o1) : (o2 > m1 ? o2 : m1);
        m1 = n1; m2 = n2;
    }
    if (lane == 0) sWarp2[warp] = m2;
    __syncthreads();
    if (warp == 0) {
        float v = (lane < 16) ? sWarp2[lane] : 3.4e38f;
#pragma unroll
        for (int off = 8; off > 0; off >>= 1) {
            float o = __shfl_down_sync(0xffffffffu, v, off);
            v = o < v ? o : v;
        }
        if (lane == 0) sThr = v - DELTA;
    }
    __syncthreads();
    const float thr = sThr;

    // phase 2: compact candidate indices
#pragma unroll
    for (int i = 0; i < 8; ++i) {
        float vv[4] = {q[i].x, q[i].y, q[i].z, q[i].w};
#pragma unroll
        for (int e = 0; e < 4; ++e) {
            if (vv[e] >= thr) {
                unsigned p = atomicAdd(&sCnt, 1u);
                if (p < CAND_CAP) candI[p] = (unsigned)(tid * 32 + i * 4 + e);
            }
        }
    }
    __syncthreads();
    const int C = (int)(sCnt < CAND_CAP ? sCnt : CAND_CAP);

    // phase 3: exact fp32 dot per candidate
    for (int b = 0; b < C; b += 512) {
        int ci = b + tid;
        if (ci < C) {
            const float4* wc = (const float4*)(W + (size_t)candI[ci] * DIM);
            float4 acc = make_float4(0.f, 0.f, 0.f, 0.f);
#pragma unroll
            for (int j = 0; j < 32; ++j) {
                float4 a = *((const float4*)sWrow + j);
                float4 bb = __ldg(wc + j);
                acc.x = fmaf(a.x, bb.x, acc.x);
                acc.y = fmaf(a.y, bb.y, acc.y);
                acc.z = fmaf(a.z, bb.z, acc.z);
                acc.w = fmaf(a.w, bb.w, acc.w);
            }
            float dot = (acc.x + acc.y) + (acc.z + acc.w);
            candV[ci] = dot;
            candK[ci] = f2key(dot);
        }
    }
    __syncthreads();

    // phase 4: exact rank (val desc, idx asc)
    for (int b = 0; b < C; b += 512) {
        int ci = b + tid;
        if (ci < C) {
            unsigned myk = candK[ci], myi = candI[ci];
            int rank = 0;
            for (int j = 0; j < C; ++j) {
                unsigned kj = candK[j];
                rank += (kj > myk) || (kj == myk && candI[j] < myi);
            }
            flags[ci] = (rank < TOPK) ? 1u : 0u;
        }
    }
    __syncthreads();

    // phase 5: column-sorted emit
    for (int b = 0; b < C; b += 512) {
        int ci = b + tid;
        if (ci < C && flags[ci]) {
            unsigned myi = candI[ci];
            int pos = 0;
            for (int j = 0; j < C; ++j)
                pos += (flags[j] && candI[j] < myi);
            const long long o = (long long)row * TOPK + pos;
            out[o]             = (float)row;
            out[NKTOT + o]     = (float)myi;
            out[2 * NKTOT + o] = candV[ci];
        }
    }
}

// ---------------- launch ----------------
extern "C" void kernel_launch(void* const* d_in, const int* in_sizes, int n_in,
                              void* d_out, int out_size) {
    const float* W = (const float*)d_in[n_in > 1 ? 1 : 0];
    if (in_sizes[0] == NROWS * DIM) W = (const float*)d_in[0];
    float* out = (float*)d_out;

    cudaFuncSetAttribute(gemm_kernel,
                         cudaFuncAttributeMaxDynamicSharedMemorySize, GEMM_SMEM);

    prep_kernel<<<(NROWS * DIM + 255) / 256, 256>>>(W);
    for (int s = 0; s < NSLABS; ++s) {
        gemm_kernel<<<dim3(NROWS / 128, SLAB / 128), 256, GEMM_SMEM>>>(s * SLAB);
        select_kernel<<<SLAB, 512>>>(W, out, s * SLAB);
    }
}